// round 10
// baseline (speedup 1.0000x reference)
#include <cuda_runtime.h>
#include <math_constants.h>
#include <stdint.h>

#define KTOP 6       // K+1 with K=5
#define TPB  128
#define CAP  1536    // candidate buffer capacity (expected ~68 used)
#define THR  3.0f    // candidate threshold; guarded by exact fallback
#define EGATE 20.0855369f   // exp(THR): conservative gate on 4-elem exp sums

__device__ float g_row_loss[8192];
__device__ unsigned int g_ticket = 0;

__device__ __forceinline__ void topk_insert(float (&t)[KTOP], float v) {
    float x = v;
    #pragma unroll
    for (int j = 0; j < KTOP; ++j) {
        float hi = fmaxf(t[j], x);
        float lo = fminf(t[j], x);
        t[j] = hi; x = lo;
    }
}

__device__ __forceinline__ void push_cand(float v, int idx, int yi,
                                          int* scnt, float* cval) {
    if (v > THR && idx != yi) {
        int pos = atomicAdd(scnt, 1);
        if (pos < CAP) cval[pos] = v;
    }
}

// exp-sum one float4 into s; candidate gate derived from the partial sum.
// exps >= 0 and exp monotone => any elem > THR forces q >= exp(THR): gate is
// conservative (never misses); false positives just re-test exactly.
__device__ __forceinline__ void proc_vec(float4 a, int base, int yi,
                                         float& s, int* scnt, float* cval) {
    float e0 = __expf(a.x), e1 = __expf(a.y), e2 = __expf(a.z), e3 = __expf(a.w);
    float q = (e0 + e1) + (e2 + e3);
    s += q;
    if (q > EGATE) {                      // rare (~1% of thread-vectors)
        push_cand(a.x, base + 0, yi, scnt, cval);
        push_cand(a.y, base + 1, yi, scnt, cval);
        push_cand(a.z, base + 2, yi, scnt, cval);
        push_cand(a.w, base + 3, yi, scnt, cval);
    }
}

__global__ __launch_bounds__(TPB) void autkc_fused_kernel(
    const float* __restrict__ pred,
    const int*   __restrict__ ylab,
    int C, int B,
    float* __restrict__ out)
{
    const int row = blockIdx.x;
    const float* __restrict__ p = pred + (long long)row * (long long)C;
    const int yi  = ylab[row];
    const int tid = threadIdx.x;

    __shared__ float cval[CAP];
    __shared__ int   scnt;
    __shared__ float shsum[TPB / 32];
    __shared__ int   is_last;

    if (tid == 0) scnt = 0;
    __syncthreads();

    float s0 = 0.f, s1 = 0.f, s2 = 0.f, s3 = 0.f;

    // ---- alignment peel (row base may not be 16B aligned; C odd) ----
    const int mis  = (int)(((uintptr_t)p & 15u) >> 2);
    const int peel = ((4 - mis) & 3);
    for (int i = tid; i < peel && i < C; i += TPB) {
        float v = p[i];
        s0 += __expf(v);
        push_cand(v, i, yi, &scnt, cval);
    }

    const int nvec = (C - peel) >> 2;
    const float4* __restrict__ pv = (const float4*)(p + peel);

    // ---- hot streaming loop: 4 front-batched LDG.128 per iteration ----
    int j = tid;
    for (; j + 3 * TPB < nvec; j += 4 * TPB) {
        float4 a = __ldcs(&pv[j]);
        float4 b = __ldcs(&pv[j +     TPB]);
        float4 c = __ldcs(&pv[j + 2 * TPB]);
        float4 d = __ldcs(&pv[j + 3 * TPB]);
        int ba = peel + 4 * j;
        proc_vec(a, ba,            yi, s0, &scnt, cval);
        proc_vec(b, ba + 4 * TPB,  yi, s1, &scnt, cval);
        proc_vec(c, ba + 8 * TPB,  yi, s2, &scnt, cval);
        proc_vec(d, ba + 12 * TPB, yi, s3, &scnt, cval);
    }
    for (; j < nvec; j += TPB) {
        float4 a = __ldcs(&pv[j]);
        proc_vec(a, peel + 4 * j, yi, s0, &scnt, cval);
    }
    for (int i = peel + 4 * nvec + tid; i < C; i += TPB) {
        float v = p[i];
        s0 += __expf(v);
        push_cand(v, i, yi, &scnt, cval);
    }

    float s = (s0 + s1) + (s2 + s3);
    #pragma unroll
    for (int o = 16; o > 0; o >>= 1) s += __shfl_down_sync(0xffffffffu, s, o);
    if ((tid & 31) == 0) shsum[tid >> 5] = s;
    __syncthreads();

    // ---- candidate count check; exact fallback for adversarial input ----
    int n = scnt;
    if (n < KTOP || n > CAP) {
        float t[KTOP];
        #pragma unroll
        for (int k = 0; k < KTOP; ++k) t[k] = -CUDART_INF_F;
        float thr2 = -CUDART_INF_F;
        for (int i = tid; i < C; i += TPB) {
            float v = p[i];
            if (v > thr2 && i != yi) { topk_insert(t, v); thr2 = t[KTOP - 1]; }
        }
        __syncthreads();
        #pragma unroll
        for (int k = 0; k < KTOP; ++k) cval[tid + k * TPB] = t[k];
        n = TPB * KTOP;
        __syncthreads();
    }

    // ---- warp-0-only top-6 + per-row loss (no extra block barriers) ----
    if (tid < 32) {
        float t[KTOP];
        #pragma unroll
        for (int k = 0; k < KTOP; ++k) t[k] = -CUDART_INF_F;
        for (int i = tid; i < n; i += 32) topk_insert(t, cval[i]);

        float S_total = 0.0f;
        #pragma unroll
        for (int w = 0; w < TPB / 32; ++w) S_total += shsum[w];
        float invS = 1.0f / S_total;
        float py   = __expf(p[yi]) * invS;

        float acc = 0.0f;
        #pragma unroll
        for (int r = 0; r < KTOP; ++r) {
            float h = t[0];
            float m = h;
            #pragma unroll
            for (int o = 16; o > 0; o >>= 1)
                m = fmaxf(m, __shfl_xor_sync(0xffffffffu, m, o));
            unsigned own = __ballot_sync(0xffffffffu, h == m);
            if (tid == (__ffs(own) - 1)) {          // extract one instance
                #pragma unroll
                for (int k = 0; k < KTOP - 1; ++k) t[k] = t[k + 1];
                t[KTOP - 1] = -CUDART_INF_F;
            }
            float pi = __expf(m) * invS;
            float dd = 1.0f + pi - py;
            acc += dd * dd;                          // all lanes redundantly
        }

        if (tid == 0) {
            g_row_loss[row] = acc * (1.0f / (float)(KTOP - 1));   // /K
            __threadfence();
            unsigned int done = atomicAdd(&g_ticket, 1u);
            is_last = (done == (unsigned int)(B - 1)) ? 1 : 0;
        }
    }
    __syncthreads();

    // ---- fused last-CTA mean ----
    if (is_last) {
        __threadfence();
        float fs = 0.0f;
        for (int i = tid; i < B; i += TPB) fs += g_row_loss[i];
        #pragma unroll
        for (int o = 16; o > 0; o >>= 1) fs += __shfl_down_sync(0xffffffffu, fs, o);
        if ((tid & 31) == 0) shsum[tid >> 5] = fs;
        __syncthreads();
        if (tid == 0) {
            float tot = 0.0f;
            #pragma unroll
            for (int w = 0; w < TPB / 32; ++w) tot += shsum[w];
            out[0] = tot / (float)B;
            g_ticket = 0;   // reset for next graph replay
        }
    }
}

extern "C" void kernel_launch(void* const* d_in, const int* in_sizes, int n_in,
                              void* d_out, int out_size)
{
    const float* pred = (const float*)d_in[0];
    const int*   y    = (const int*)d_in[1];
    // d_in[2] = epoch, unused (AUTKC branch taken for epoch >= 0)

    const int B = in_sizes[1];
    const int C = in_sizes[0] / B;

    autkc_fused_kernel<<<B, TPB>>>(pred, y, C, B, (float*)d_out);
}

// round 11
// speedup vs baseline: 1.0707x; 1.0707x over previous
#include <cuda_runtime.h>
#include <math_constants.h>
#include <stdint.h>

#define KTOP 6       // K+1 with K=5
#define TPB  128
#define CAP  1536    // candidate buffer capacity (expected ~68 used)
#define THR  3.0f    // candidate threshold; guarded by exact fallback
#define EGATE 20.0855369f   // exp(THR): conservative gate on 4-elem exp sums

__device__ float g_row_loss[8192];
__device__ unsigned int g_ticket = 0;

__device__ __forceinline__ void topk_insert(float (&t)[KTOP], float v) {
    float x = v;
    #pragma unroll
    for (int j = 0; j < KTOP; ++j) {
        float hi = fmaxf(t[j], x);
        float lo = fminf(t[j], x);
        t[j] = hi; x = lo;
    }
}

__device__ __forceinline__ void push_cand(float v, int idx, int yi,
                                          int* scnt, float* cval) {
    if (v > THR && idx != yi) {
        int pos = atomicAdd(scnt, 1);
        if (pos < CAP) cval[pos] = v;
    }
}

// exp-sum one float4 into s; candidate gate derived from the partial sum.
// exps >= 0 and exp monotone => any elem > THR forces q >= exp(THR): gate is
// conservative (never misses); false positives just re-test exactly.
__device__ __forceinline__ void proc_vec(float4 a, int base, int yi,
                                         float& s, int* scnt, float* cval) {
    float e0 = __expf(a.x), e1 = __expf(a.y), e2 = __expf(a.z), e3 = __expf(a.w);
    float q = (e0 + e1) + (e2 + e3);
    s += q;
    if (q > EGATE) {                      // rare (~1% of thread-vectors)
        push_cand(a.x, base + 0, yi, scnt, cval);
        push_cand(a.y, base + 1, yi, scnt, cval);
        push_cand(a.z, base + 2, yi, scnt, cval);
        push_cand(a.w, base + 3, yi, scnt, cval);
    }
}

// minBlocksPerMultiprocessor=16 pins the register budget at 32 (64K regfile /
// (16 CTAs * 128 thr)) — occupancy is the binding resource for this kernel.
__global__ __launch_bounds__(TPB, 16) void autkc_fused_kernel(
    const float* __restrict__ pred,
    const int*   __restrict__ ylab,
    int C, int B,
    float* __restrict__ out)
{
    const int row = blockIdx.x;
    const float* __restrict__ p = pred + (long long)row * (long long)C;
    const int yi  = ylab[row];
    const int tid = threadIdx.x;

    __shared__ float cval[CAP];
    __shared__ int   scnt;
    __shared__ float shsum[TPB / 32];
    __shared__ float wval[TPB / 32];
    __shared__ int   widx[TPB / 32];
    __shared__ float topv[KTOP];
    __shared__ int   is_last;

    if (tid == 0) scnt = 0;
    __syncthreads();

    float s0 = 0.f, s1 = 0.f, s2 = 0.f, s3 = 0.f;

    // ---- alignment peel (row base may not be 16B aligned; C odd) ----
    const int mis  = (int)(((uintptr_t)p & 15u) >> 2);
    const int peel = ((4 - mis) & 3);
    for (int i = tid; i < peel && i < C; i += TPB) {
        float v = p[i];
        s0 += __expf(v);
        push_cand(v, i, yi, &scnt, cval);
    }

    const int nvec = (C - peel) >> 2;
    const float4* __restrict__ pv = (const float4*)(p + peel);

    // ---- hot streaming loop: 4 front-batched LDG.128 per iteration ----
    int j = tid;
    for (; j + 3 * TPB < nvec; j += 4 * TPB) {
        float4 a = __ldcs(&pv[j]);
        float4 b = __ldcs(&pv[j +     TPB]);
        float4 c = __ldcs(&pv[j + 2 * TPB]);
        float4 d = __ldcs(&pv[j + 3 * TPB]);
        int ba = peel + 4 * j;
        proc_vec(a, ba,            yi, s0, &scnt, cval);
        proc_vec(b, ba + 4 * TPB,  yi, s1, &scnt, cval);
        proc_vec(c, ba + 8 * TPB,  yi, s2, &scnt, cval);
        proc_vec(d, ba + 12 * TPB, yi, s3, &scnt, cval);
    }
    for (; j < nvec; j += TPB) {
        float4 a = __ldcs(&pv[j]);
        proc_vec(a, peel + 4 * j, yi, s0, &scnt, cval);
    }
    for (int i = peel + 4 * nvec + tid; i < C; i += TPB) {
        float v = p[i];
        s0 += __expf(v);
        push_cand(v, i, yi, &scnt, cval);
    }

    float s = (s0 + s1) + (s2 + s3);
    #pragma unroll
    for (int o = 16; o > 0; o >>= 1) s += __shfl_down_sync(0xffffffffu, s, o);
    if ((tid & 31) == 0) shsum[tid >> 5] = s;
    __syncthreads();

    // ---- candidate count check; exact fallback for adversarial input ----
    int n = scnt;
    if (n < KTOP || n > CAP) {
        float t[KTOP];
        #pragma unroll
        for (int k = 0; k < KTOP; ++k) t[k] = -CUDART_INF_F;
        float thr2 = -CUDART_INF_F;
        for (int i = tid; i < C; i += TPB) {
            float v = p[i];
            if (v > thr2 && i != yi) { topk_insert(t, v); thr2 = t[KTOP - 1]; }
        }
        __syncthreads();
        #pragma unroll
        for (int k = 0; k < KTOP; ++k) cval[tid + k * TPB] = t[k];
        n = TPB * KTOP;
        __syncthreads();
    }

    // ---- top-6 of cval[0..n): 6 masked argmax rounds ----
    for (int r = 0; r < KTOP; ++r) {
        float bv = -CUDART_INF_F;
        int   bi = 0;
        for (int i = tid; i < n; i += TPB) {
            float v = cval[i];
            if (v > bv) { bv = v; bi = i; }
        }
        #pragma unroll
        for (int o = 16; o > 0; o >>= 1) {
            float ov = __shfl_down_sync(0xffffffffu, bv, o);
            int   oi = __shfl_down_sync(0xffffffffu, bi, o);
            if (ov > bv) { bv = ov; bi = oi; }
        }
        if ((tid & 31) == 0) { wval[tid >> 5] = bv; widx[tid >> 5] = bi; }
        __syncthreads();
        if (tid == 0) {
            float best = -CUDART_INF_F;
            int   besti = 0;
            #pragma unroll
            for (int w = 0; w < TPB / 32; ++w)
                if (wval[w] > best) { best = wval[w]; besti = widx[w]; }
            topv[r] = best;
            cval[besti] = -CUDART_INF_F;
        }
        __syncthreads();
    }

    // ---- per-row loss + fused last-CTA mean ----
    if (tid == 0) {
        float S_total = 0.0f;
        #pragma unroll
        for (int w = 0; w < TPB / 32; ++w) S_total += shsum[w];
        float invS = 1.0f / S_total;
        float py   = __expf(p[yi]) * invS;
        float acc  = 0.0f;
        #pragma unroll
        for (int r = 0; r < KTOP; ++r) {
            float pi = __expf(topv[r]) * invS;
            float dd = 1.0f + pi - py;
            acc += dd * dd;
        }
        g_row_loss[row] = acc * (1.0f / (float)(KTOP - 1));   // /K
        __threadfence();
        unsigned int done = atomicAdd(&g_ticket, 1u);
        is_last = (done == (unsigned int)(B - 1)) ? 1 : 0;
    }
    __syncthreads();

    if (is_last) {
        __threadfence();
        float fs = 0.0f;
        for (int i = tid; i < B; i += TPB) fs += g_row_loss[i];
        #pragma unroll
        for (int o = 16; o > 0; o >>= 1) fs += __shfl_down_sync(0xffffffffu, fs, o);
        if ((tid & 31) == 0) shsum[tid >> 5] = fs;
        __syncthreads();
        if (tid == 0) {
            float tot = 0.0f;
            #pragma unroll
            for (int w = 0; w < TPB / 32; ++w) tot += shsum[w];
            out[0] = tot / (float)B;
            g_ticket = 0;   // reset for next graph replay
        }
    }
}

extern "C" void kernel_launch(void* const* d_in, const int* in_sizes, int n_in,
                              void* d_out, int out_size)
{
    const float* pred = (const float*)d_in[0];
    const int*   y    = (const int*)d_in[1];
    // d_in[2] = epoch, unused (AUTKC branch taken for epoch >= 0)

    const int B = in_sizes[1];
    const int C = in_sizes[0] / B;

    autkc_fused_kernel<<<B, TPB>>>(pred, y, C, B, (float*)d_out);
}

// round 12
// speedup vs baseline: 1.1129x; 1.0394x over previous
#include <cuda_runtime.h>
#include <math_constants.h>
#include <stdint.h>

#define KTOP 6       // K+1 with K=5
#define TPB  128
#define CAP  1536    // candidate buffer capacity (expected ~68 used)
#define THR  3.0f    // candidate threshold; guarded by exact fallback
#define EGATE 20.0855369f   // exp(THR): conservative gate on 4-elem exp sums

__device__ float g_row_loss[8192];
__device__ unsigned int g_ticket = 0;

__device__ __forceinline__ void topk_insert(float (&t)[KTOP], float v) {
    float x = v;
    #pragma unroll
    for (int j = 0; j < KTOP; ++j) {
        float hi = fmaxf(t[j], x);
        float lo = fminf(t[j], x);
        t[j] = hi; x = lo;
    }
}

__device__ __forceinline__ void push_cand(float v, int idx, int yi,
                                          int* scnt, float* cval) {
    if (v > THR && idx != yi) {
        int pos = atomicAdd(scnt, 1);
        if (pos < CAP) cval[pos] = v;
    }
}

// exp-sum one float4 into s; candidate gate derived from the partial sum.
// exps >= 0 and exp monotone => any elem > THR forces q >= exp(THR): gate is
// conservative (never misses); false positives just re-test exactly.
__device__ __forceinline__ void proc_vec(float4 a, int base, int yi,
                                         float& s, int* scnt, float* cval) {
    float e0 = __expf(a.x), e1 = __expf(a.y), e2 = __expf(a.z), e3 = __expf(a.w);
    float q = (e0 + e1) + (e2 + e3);
    s += q;
    if (q > EGATE) {                      // rare (~1% of thread-vectors)
        push_cand(a.x, base + 0, yi, scnt, cval);
        push_cand(a.y, base + 1, yi, scnt, cval);
        push_cand(a.z, base + 2, yi, scnt, cval);
        push_cand(a.w, base + 3, yi, scnt, cval);
    }
}

// minBlocksPerMultiprocessor=16 pins the register budget at 32 (64K regfile /
// (16 CTAs * 128 thr)) — occupancy is the binding resource for this kernel.
__global__ __launch_bounds__(TPB, 16) void autkc_fused_kernel(
    const float* __restrict__ pred,
    const int*   __restrict__ ylab,
    int C, int B,
    float* __restrict__ out)
{
    const int row = blockIdx.x;
    const float* __restrict__ p = pred + (long long)row * (long long)C;
    const int yi  = ylab[row];
    const int tid = threadIdx.x;

    __shared__ float cval[CAP];
    __shared__ int   scnt;
    __shared__ float shsum[TPB / 32];
    __shared__ float wval[TPB / 32];
    __shared__ int   widx[TPB / 32];
    __shared__ float topv[KTOP];
    __shared__ float sh_ylogit;
    __shared__ int   is_last;

    if (tid == 0) {
        scnt = 0;
        sh_ylogit = p[yi];    // cold fetch overlaps the whole streaming loop
    }
    __syncthreads();

    float s0 = 0.f, s1 = 0.f, s2 = 0.f, s3 = 0.f;

    // ---- alignment peel (row base may not be 16B aligned; C odd) ----
    const int mis  = (int)(((uintptr_t)p & 15u) >> 2);
    const int peel = ((4 - mis) & 3);
    for (int i = tid; i < peel && i < C; i += TPB) {
        float v = p[i];
        s0 += __expf(v);
        push_cand(v, i, yi, &scnt, cval);
    }

    const int nvec = (C - peel) >> 2;
    const float4* __restrict__ pv = (const float4*)(p + peel);

    // ---- hot streaming loop: 4 front-batched LDG.128 per iteration ----
    int j = tid;
    for (; j + 3 * TPB < nvec; j += 4 * TPB) {
        float4 a = __ldcs(&pv[j]);
        float4 b = __ldcs(&pv[j +     TPB]);
        float4 c = __ldcs(&pv[j + 2 * TPB]);
        float4 d = __ldcs(&pv[j + 3 * TPB]);
        int ba = peel + 4 * j;
        proc_vec(a, ba,            yi, s0, &scnt, cval);
        proc_vec(b, ba + 4 * TPB,  yi, s1, &scnt, cval);
        proc_vec(c, ba + 8 * TPB,  yi, s2, &scnt, cval);
        proc_vec(d, ba + 12 * TPB, yi, s3, &scnt, cval);
    }
    for (; j < nvec; j += TPB) {
        float4 a = __ldcs(&pv[j]);
        proc_vec(a, peel + 4 * j, yi, s0, &scnt, cval);
    }
    for (int i = peel + 4 * nvec + tid; i < C; i += TPB) {
        float v = p[i];
        s0 += __expf(v);
        push_cand(v, i, yi, &scnt, cval);
    }

    float s = (s0 + s1) + (s2 + s3);
    #pragma unroll
    for (int o = 16; o > 0; o >>= 1) s += __shfl_down_sync(0xffffffffu, s, o);
    if ((tid & 31) == 0) shsum[tid >> 5] = s;
    __syncthreads();

    // ---- candidate count check; exact fallback for adversarial input ----
    int n = scnt;
    if (n < KTOP || n > CAP) {
        float t[KTOP];
        #pragma unroll
        for (int k = 0; k < KTOP; ++k) t[k] = -CUDART_INF_F;
        float thr2 = -CUDART_INF_F;
        for (int i = tid; i < C; i += TPB) {
            float v = p[i];
            if (v > thr2 && i != yi) { topk_insert(t, v); thr2 = t[KTOP - 1]; }
        }
        __syncthreads();
        #pragma unroll
        for (int k = 0; k < KTOP; ++k) cval[tid + k * TPB] = t[k];
        n = TPB * KTOP;
        __syncthreads();
    }

    // ---- top-6 of cval[0..n): 6 masked argmax rounds ----
    for (int r = 0; r < KTOP; ++r) {
        float bv = -CUDART_INF_F;
        int   bi = 0;
        for (int i = tid; i < n; i += TPB) {
            float v = cval[i];
            if (v > bv) { bv = v; bi = i; }
        }
        #pragma unroll
        for (int o = 16; o > 0; o >>= 1) {
            float ov = __shfl_down_sync(0xffffffffu, bv, o);
            int   oi = __shfl_down_sync(0xffffffffu, bi, o);
            if (ov > bv) { bv = ov; bi = oi; }
        }
        if ((tid & 31) == 0) { wval[tid >> 5] = bv; widx[tid >> 5] = bi; }
        __syncthreads();
        if (tid == 0) {
            float best = -CUDART_INF_F;
            int   besti = 0;
            #pragma unroll
            for (int w = 0; w < TPB / 32; ++w)
                if (wval[w] > best) { best = wval[w]; besti = widx[w]; }
            topv[r] = best;
            cval[besti] = -CUDART_INF_F;
        }
        __syncthreads();
    }

    // ---- per-row loss + fused last-CTA mean ----
    if (tid == 0) {
        float S_total = 0.0f;
        #pragma unroll
        for (int w = 0; w < TPB / 32; ++w) S_total += shsum[w];
        float invS = 1.0f / S_total;
        float py   = __expf(sh_ylogit) * invS;
        float acc  = 0.0f;
        #pragma unroll
        for (int r = 0; r < KTOP; ++r) {
            float pi = __expf(topv[r]) * invS;
            float dd = 1.0f + pi - py;
            acc += dd * dd;
        }
        g_row_loss[row] = acc * (1.0f / (float)(KTOP - 1));   // /K
        __threadfence();
        unsigned int done = atomicAdd(&g_ticket, 1u);
        is_last = (done == (unsigned int)(B - 1)) ? 1 : 0;
    }
    __syncthreads();

    if (is_last) {
        __threadfence();
        float fs = 0.0f;
        for (int i = tid; i < B; i += TPB) fs += g_row_loss[i];
        #pragma unroll
        for (int o = 16; o > 0; o >>= 1) fs += __shfl_down_sync(0xffffffffu, fs, o);
        if ((tid & 31) == 0) shsum[tid >> 5] = fs;
        __syncthreads();
        if (tid == 0) {
            float tot = 0.0f;
            #pragma unroll
            for (int w = 0; w < TPB / 32; ++w) tot += shsum[w];
            out[0] = tot / (float)B;
            g_ticket = 0;   // reset for next graph replay
        }
    }
}

extern "C" void kernel_launch(void* const* d_in, const int* in_sizes, int n_in,
                              void* d_out, int out_size)
{
    const float* pred = (const float*)d_in[0];
    const int*   y    = (const int*)d_in[1];
    // d_in[2] = epoch, unused (AUTKC branch taken for epoch >= 0)

    const int B = in_sizes[1];
    const int C = in_sizes[0] / B;

    autkc_fused_kernel<<<B, TPB>>>(pred, y, C, B, (float*)d_out);
}